// round 3
// baseline (speedup 1.0000x reference)
#include <cuda_runtime.h>
#include <stdint.h>

#define NCH   1024
#define HW    65536          // 256*256 elements per channel
#define TOPK  256

// Sanctioned scratch (no allocations allowed anywhere).
__device__ float g_means[NCH];

// ---------------------------------------------------------------------------
// Kernel 1: one CTA per channel. 256 threads, each sums 64 coalesced float4s
// (high MLP -> DRAM latency hidden), warp-shuffle reduce + tiny smem tail.
// ---------------------------------------------------------------------------
__global__ void __launch_bounds__(256) channel_mean_kernel(const float* __restrict__ x) {
    const int c = blockIdx.x;
    const int t = threadIdx.x;

    const float4* __restrict__ p =
        reinterpret_cast<const float4*>(x) + (size_t)c * (HW / 4);

    float s = 0.0f;
    // HW/4 = 16384 float4s per channel; 256 threads -> 64 iters each.
    #pragma unroll 8
    for (int i = 0; i < 64; ++i) {
        float4 v = p[i * 256 + t];
        s += (v.x + v.y) + (v.z + v.w);
    }

    // Warp reduction
    #pragma unroll
    for (int o = 16; o > 0; o >>= 1)
        s += __shfl_down_sync(0xffffffffu, s, o);

    __shared__ float sh[8];
    if ((t & 31) == 0) sh[t >> 5] = s;
    __syncthreads();

    if (t == 0) {
        float tot = sh[0];
        #pragma unroll
        for (int w = 1; w < 8; ++w) tot += sh[w];
        g_means[c] = tot * (1.0f / (float)HW);
    }
}

// ---------------------------------------------------------------------------
// Kernel 2: single CTA, 1024 threads. Brute-force ranking — thread t counts
// channels strictly better than t (greater mean, or equal mean with smaller
// index). rank < TOPK  =>  out[rank] = t. Reproduces jax.lax.top_k ordering
// (descending value, ascending index on ties) exactly; each output slot is
// written by exactly one thread.
//
// OUTPUT IS WRITTEN AS float32: the harness's declared output dtype is fp32
// (indices 0..1023 are exactly representable). Writing raw int32 bit patterns
// read back as denormals ~0, which produced the rel_err == 1.0 signature.
// ---------------------------------------------------------------------------
__global__ void __launch_bounds__(NCH) rank_kernel(float* __restrict__ out) {
    __shared__ float sm[NCH];
    const int t = threadIdx.x;
    sm[t] = g_means[t];
    __syncthreads();

    const float mv = sm[t];
    int rank = 0;
    #pragma unroll 8
    for (int j = 0; j < NCH; ++j) {
        float o = sm[j];
        rank += (int)((o > mv) || (o == mv && j < t));
    }
    if (rank < TOPK) out[rank] = (float)t;
}

// ---------------------------------------------------------------------------
extern "C" void kernel_launch(void* const* d_in, const int* in_sizes, int n_in,
                              void* d_out, int out_size) {
    // Robustly locate the image tensor: the input with exactly NCH*HW elements
    // (guards against any extra small inputs preceding it).
    int xi = 0;
    long long want = (long long)NCH * (long long)HW;
    long long best = -1;
    for (int i = 0; i < n_in; ++i) {
        long long sz = (long long)in_sizes[i];
        if (sz == want) { xi = i; break; }
        if (sz > best) { best = sz; xi = i; }
    }
    const float* x = (const float*)d_in[xi];
    float* out = (float*)d_out;

    channel_mean_kernel<<<NCH, 256>>>(x);
    rank_kernel<<<1, NCH>>>(out);
}

// round 4
// speedup vs baseline: 1.6080x; 1.6080x over previous
#include <cuda_runtime.h>
#include <stdint.h>

#define NCH   1024
#define HW    65536          // 256*256 elements per channel
#define TOPK  256

// Sanctioned scratch (no allocations allowed anywhere).
__device__ float g_means[NCH];

// ---------------------------------------------------------------------------
// Kernel 1: one CTA per channel. 256 threads, each sums 64 coalesced float4s
// (high MLP -> DRAM latency hidden), warp-shuffle reduce + tiny smem tail.
// ~40us = HBM roofline for 256 MiB read.
// ---------------------------------------------------------------------------
__global__ void __launch_bounds__(256) channel_mean_kernel(const float* __restrict__ x) {
    const int c = blockIdx.x;
    const int t = threadIdx.x;

    const float4* __restrict__ p =
        reinterpret_cast<const float4*>(x) + (size_t)c * (HW / 4);

    float s = 0.0f;
    // HW/4 = 16384 float4s per channel; 256 threads -> 64 iters each.
    #pragma unroll 8
    for (int i = 0; i < 64; ++i) {
        float4 v = p[i * 256 + t];
        s += (v.x + v.y) + (v.z + v.w);
    }

    // Warp reduction
    #pragma unroll
    for (int o = 16; o > 0; o >>= 1)
        s += __shfl_down_sync(0xffffffffu, s, o);

    __shared__ float sh[8];
    if ((t & 31) == 0) sh[t >> 5] = s;
    __syncthreads();

    if (t == 0) {
        float tot = sh[0];
        #pragma unroll
        for (int w = 1; w < 8; ++w) tot += sh[w];
        g_means[c] = tot * (1.0f / (float)HW);
    }
}

// ---------------------------------------------------------------------------
// Kernel 2 (grid-parallel rank-by-count): block c ranks channel c.
// 256 threads each compare one float4 of g_means (coalesced, L2-hot: whole
// array is 4KB), block-reduce the count, thread 0 writes out[rank] = c if
// rank < TOPK. Reproduces jax.lax.top_k ordering exactly (descending value,
// ascending index on ties); each output slot written by exactly one block.
// Previous single-CTA version was issue-bound on one SM (33.7us); this
// spreads the 1M comparisons over all SMs.
// ---------------------------------------------------------------------------
__global__ void __launch_bounds__(256) rank_kernel(float* __restrict__ out) {
    const int c = blockIdx.x;
    const int t = threadIdx.x;

    const float mv = g_means[c];
    const float4 v = reinterpret_cast<const float4*>(g_means)[t];
    const int j0 = t * 4;

    int cnt = 0;
    cnt += (int)((v.x > mv) || (v.x == mv && (j0 + 0) < c));
    cnt += (int)((v.y > mv) || (v.y == mv && (j0 + 1) < c));
    cnt += (int)((v.z > mv) || (v.z == mv && (j0 + 2) < c));
    cnt += (int)((v.w > mv) || (v.w == mv && (j0 + 3) < c));

    // Warp reduction
    #pragma unroll
    for (int o = 16; o > 0; o >>= 1)
        cnt += __shfl_down_sync(0xffffffffu, cnt, o);

    __shared__ int sh[8];
    if ((t & 31) == 0) sh[t >> 5] = cnt;
    __syncthreads();

    if (t == 0) {
        int rank = sh[0];
        #pragma unroll
        for (int w = 1; w < 8; ++w) rank += sh[w];
        if (rank < TOPK) out[rank] = (float)c;
    }
}

// ---------------------------------------------------------------------------
extern "C" void kernel_launch(void* const* d_in, const int* in_sizes, int n_in,
                              void* d_out, int out_size) {
    // Robustly locate the image tensor: the input with exactly NCH*HW elements.
    int xi = 0;
    long long want = (long long)NCH * (long long)HW;
    long long best = -1;
    for (int i = 0; i < n_in; ++i) {
        long long sz = (long long)in_sizes[i];
        if (sz == want) { xi = i; break; }
        if (sz > best) { best = sz; xi = i; }
    }
    const float* x = (const float*)d_in[xi];
    float* out = (float*)d_out;

    channel_mean_kernel<<<NCH, 256>>>(x);
    rank_kernel<<<NCH, 256>>>(out);
}

// round 5
// speedup vs baseline: 1.6159x; 1.0049x over previous
#include <cuda_runtime.h>
#include <stdint.h>

#define NCH   1024
#define HW    65536          // 256*256 elements per channel
#define TOPK  256

// Sanctioned scratch (no allocations allowed anywhere).
__device__ float    g_means[NCH];
__device__ unsigned g_ctr;        // monotonic arrival counter (never reset;
                                  // generation = ticket/NCH, works across
                                  // graph replays deterministically)

// ---------------------------------------------------------------------------
// Fused kernel: one CTA per channel.
// Phase 1: stream-reduce this channel's 64K floats (HBM-bound, ~40us chip-wide).
// Barrier: one-wave grid barrier. launch_bounds(256,8) guarantees 8 CTAs/SM
//          => 1184 resident slots >= 1024 CTAs => whole grid co-resident in
//          wave 1, so the spin cannot deadlock. Ticket-based generation
//          counter needs no reset between graph replays.
// Phase 2: each CTA ranks its own channel against the (L2-hot) means array
//          and writes out[rank] = c if rank < TOPK. Reproduces jax.lax.top_k
//          ordering exactly (descending value, ascending index on ties);
//          every output slot is written by exactly one CTA.
// ---------------------------------------------------------------------------
__global__ void __launch_bounds__(256, 8)
fused_rank_kernel(const float* __restrict__ x, float* __restrict__ out) {
    const int c = blockIdx.x;
    const int t = threadIdx.x;

    // ---- Phase 1: channel mean -------------------------------------------
    const float4* __restrict__ p =
        reinterpret_cast<const float4*>(x) + (size_t)c * (HW / 4);

    float s = 0.0f;
    #pragma unroll 8
    for (int i = 0; i < 64; ++i) {
        float4 v = p[i * 256 + t];
        s += (v.x + v.y) + (v.z + v.w);
    }

    #pragma unroll
    for (int o = 16; o > 0; o >>= 1)
        s += __shfl_down_sync(0xffffffffu, s, o);

    __shared__ float shf[8];
    if ((t & 31) == 0) shf[t >> 5] = s;
    __syncthreads();

    if (t == 0) {
        float tot = shf[0];
        #pragma unroll
        for (int w = 1; w < 8; ++w) tot += shf[w];
        g_means[c] = tot * (1.0f / (float)HW);
    }

    // ---- One-wave grid barrier (release/acquire) -------------------------
    if (t == 0) {
        __threadfence();                                   // publish g_means[c]
        unsigned ticket = atomicAdd(&g_ctr, 1u);
        unsigned target = (ticket / (unsigned)NCH + 1u) * (unsigned)NCH;
        while (*(volatile unsigned*)&g_ctr < target)
            __nanosleep(64);
    }
    __syncthreads();
    __threadfence();                                       // acquire

    // ---- Phase 2: rank-by-count for channel c (means are L2-hot, 4KB) ----
    const float  mv = g_means[c];
    const float4 v  = reinterpret_cast<const float4*>(g_means)[t];
    const int    j0 = t * 4;

    int cnt = 0;
    cnt += (int)((v.x > mv) || (v.x == mv && (j0 + 0) < c));
    cnt += (int)((v.y > mv) || (v.y == mv && (j0 + 1) < c));
    cnt += (int)((v.z > mv) || (v.z == mv && (j0 + 2) < c));
    cnt += (int)((v.w > mv) || (v.w == mv && (j0 + 3) < c));

    #pragma unroll
    for (int o = 16; o > 0; o >>= 1)
        cnt += __shfl_down_sync(0xffffffffu, cnt, o);

    __shared__ int shi[8];
    if ((t & 31) == 0) shi[t >> 5] = cnt;
    __syncthreads();

    if (t == 0) {
        int rank = shi[0];
        #pragma unroll
        for (int w = 1; w < 8; ++w) rank += shi[w];
        if (rank < TOPK) out[rank] = (float)c;   // output dtype is fp32
    }
}

// ---------------------------------------------------------------------------
extern "C" void kernel_launch(void* const* d_in, const int* in_sizes, int n_in,
                              void* d_out, int out_size) {
    // Robustly locate the image tensor: the input with exactly NCH*HW elements.
    int xi = 0;
    long long want = (long long)NCH * (long long)HW;
    long long best = -1;
    for (int i = 0; i < n_in; ++i) {
        long long sz = (long long)in_sizes[i];
        if (sz == want) { xi = i; break; }
        if (sz > best) { best = sz; xi = i; }
    }
    const float* x = (const float*)d_in[xi];
    float* out = (float*)d_out;

    fused_rank_kernel<<<NCH, 256>>>(x, out);
}